// round 1
// baseline (speedup 1.0000x reference)
#include <cuda_runtime.h>
#include <math.h>

#define NN 100000
#define NE 1200000
#define FIN 128
#define FHID 64
#define FOUT 40

// ---------------- scratch (device globals: sanctioned, no allocation) ----------------
__device__ int   g_deg[NN];
__device__ int   g_rowptr[NN + 1];
__device__ int   g_cursor[NN];
__device__ int   g_col[NE];
__device__ float g_dis[NN];
__device__ float g_H[(size_t)NN * FHID];  // dis-scaled transform buffer
__device__ float g_Z[(size_t)NN * FHID];  // aggregated buffer
__device__ int   g_blksum[128];
__device__ int   g_blkoff[128];
__device__ int   g_is64;

constexpr int SCAN_B = 1024;
constexpr int NBLK   = (NN + SCAN_B - 1) / SCAN_B;  // 98

// ---------------- edge dtype detection (int64 vs int32) ----------------
// If edge_index is int64 (little-endian), every odd 32-bit word is a high word
// of a value < 2^31 -> zero. If int32, odd words are random indices (~0 w.p. ~0).
__global__ void k_detect(const int* __restrict__ e) {
    if (threadIdx.x == 0) {
        int f = 1;
        for (int i = 1; i < 256; i += 2)
            if (e[i] != 0) { f = 0; break; }
        g_is64 = f;
    }
}

__device__ __forceinline__ int edge_at(const void* e, long long idx) {
    if (g_is64) return (int)((const long long*)e)[idx];
    return ((const int*)e)[idx];
}

// ---------------- degree / dis ----------------
__global__ void k_init() {
    int i = blockIdx.x * blockDim.x + threadIdx.x;
    if (i < NN) g_deg[i] = 0;
}

__global__ void k_hist(const void* __restrict__ e) {
    int i = blockIdx.x * blockDim.x + threadIdx.x;
    if (i < NE) {
        int d = edge_at(e, (long long)NE + i);
        atomicAdd(&g_deg[d], 1);
    }
}

__global__ void k_dis() {
    int i = blockIdx.x * blockDim.x + threadIdx.x;
    if (i < NN) g_dis[i] = rsqrtf((float)(g_deg[i] + 1));
}

// ---------------- prefix scan (3 kernels) ----------------
__global__ void k_scan1() {
    __shared__ int s[SCAN_B];
    int tid = threadIdx.x;
    int idx = blockIdx.x * SCAN_B + tid;
    int v = (idx < NN) ? g_deg[idx] : 0;
    s[tid] = v;
    __syncthreads();
#pragma unroll
    for (int off = 1; off < SCAN_B; off <<= 1) {
        int t = (tid >= off) ? s[tid - off] : 0;
        __syncthreads();
        s[tid] += t;
        __syncthreads();
    }
    if (idx < NN) g_rowptr[idx + 1] = s[tid];
    if (tid == SCAN_B - 1) g_blksum[blockIdx.x] = s[tid];
}

__global__ void k_scan2() {
    __shared__ int s[128];
    int tid = threadIdx.x;
    int v = (tid < NBLK) ? g_blksum[tid] : 0;
    s[tid] = v;
    __syncthreads();
#pragma unroll
    for (int off = 1; off < 128; off <<= 1) {
        int t = (tid >= off) ? s[tid - off] : 0;
        __syncthreads();
        s[tid] += t;
        __syncthreads();
    }
    g_blkoff[tid] = s[tid] - v;  // exclusive
}

__global__ void k_scan3() {
    int i = blockIdx.x * blockDim.x + threadIdx.x;
    if (i < NN) g_rowptr[i + 1] += g_blkoff[i >> 10];
    if (i == 0) g_rowptr[0] = 0;
}

__global__ void k_cursor() {
    int i = blockIdx.x * blockDim.x + threadIdx.x;
    if (i < NN) g_cursor[i] = g_rowptr[i];
}

__global__ void k_fill(const void* __restrict__ e) {
    int i = blockIdx.x * blockDim.x + threadIdx.x;
    if (i < NE) {
        int d = edge_at(e, (long long)NE + i);
        int s = edge_at(e, i);
        int pos = atomicAdd(&g_cursor[d], 1);
        g_col[pos] = s;
    }
}

// ---------------- GEMM: out[i,c] = dis[i] * sum_k X[i,k]*W[k,c] ----------------
// Tile 64(M) x 64(N), 128 threads, each thread 8x4 outputs, K chunked by 32.
template <int K, int NOUT>
__global__ void __launch_bounds__(128) k_gemm(const float* __restrict__ X,
                                              const float* __restrict__ W,
                                              float* __restrict__ out) {
    constexpr int BM = 64;
    constexpr int BN = 64;
    constexpr int KC = 32;
    __shared__ float Ws[K][BN];
    __shared__ float Xs[KC][BM + 4];  // pad: stride 68 floats

    int t  = threadIdx.x;
    int m0 = blockIdx.x * BM;
    int rbase = (t >> 4) * 8;   // 0..56
    int cbase = (t & 15) * 4;   // 0..60

    // load W (zero-pad cols >= NOUT)
    for (int i = t; i < K * BN; i += 128) {
        int k = i / BN, c = i % BN;
        Ws[k][c] = (c < NOUT) ? W[k * NOUT + c] : 0.0f;
    }

    float acc[8][4];
#pragma unroll
    for (int j = 0; j < 8; j++)
#pragma unroll
        for (int c = 0; c < 4; c++) acc[j][c] = 0.0f;

    __syncthreads();

    for (int kc = 0; kc < K; kc += KC) {
        // load X chunk transposed: Xs[kk][row]
#pragma unroll
        for (int i = 0; i < 4; i++) {
            int v = t + i * 128;      // 0..511
            int r = v >> 3;           // 0..63
            int q = v & 7;            // float4 within 32-float chunk
            int row = m0 + r;
            float4 f = make_float4(0.f, 0.f, 0.f, 0.f);
            if (row < NN)
                f = *(const float4*)&X[(size_t)row * K + kc + q * 4];
            Xs[q * 4 + 0][r] = f.x;
            Xs[q * 4 + 1][r] = f.y;
            Xs[q * 4 + 2][r] = f.z;
            Xs[q * 4 + 3][r] = f.w;
        }
        __syncthreads();

#pragma unroll
        for (int kk = 0; kk < KC; kk++) {
            float4 wv = *(const float4*)&Ws[kc + kk][cbase];
            float4 xa = *(const float4*)&Xs[kk][rbase];
            float4 xb = *(const float4*)&Xs[kk][rbase + 4];
            float xr[8] = {xa.x, xa.y, xa.z, xa.w, xb.x, xb.y, xb.z, xb.w};
#pragma unroll
            for (int j = 0; j < 8; j++) {
                acc[j][0] = fmaf(xr[j], wv.x, acc[j][0]);
                acc[j][1] = fmaf(xr[j], wv.y, acc[j][1]);
                acc[j][2] = fmaf(xr[j], wv.z, acc[j][2]);
                acc[j][3] = fmaf(xr[j], wv.w, acc[j][3]);
            }
        }
        __syncthreads();
    }

    // epilogue: scale by dis[row]
#pragma unroll
    for (int j = 0; j < 8; j++) {
        int row = m0 + rbase + j;
        if (row < NN) {
            float ds = g_dis[row];
#pragma unroll
            for (int c = 0; c < 4; c++) {
                int cc = cbase + c;
                if (cc < NOUT)
                    out[(size_t)row * NOUT + cc] = acc[j][c] * ds;
            }
        }
    }
}

// ---------------- aggregation: warp per node ----------------
// out[i] = relu?( dis[i]*(sum_{s->i} Hs[s] + Hs[i]) + b )
template <int F, bool RELU>
__global__ void __launch_bounds__(256) k_agg(const float* __restrict__ H,
                                             const float* __restrict__ bias,
                                             float* __restrict__ out) {
    constexpr int L = F / 2;  // active lanes (float2 each)
    int warp = (blockIdx.x * blockDim.x + threadIdx.x) >> 5;
    int lane = threadIdx.x & 31;
    if (warp >= NN) return;

    const float2* H2 = (const float2*)H;
    int s = g_rowptr[warp];
    int e = g_rowptr[warp + 1];

    float ax = 0.f, ay = 0.f;
    if (lane < L) {
        float2 self = H2[(size_t)warp * L + lane];
        ax = self.x; ay = self.y;
    }

    int j = s;
    for (; j + 4 <= e; j += 4) {
        int i0 = g_col[j], i1 = g_col[j + 1], i2 = g_col[j + 2], i3 = g_col[j + 3];
        if (lane < L) {
            float2 a = H2[(size_t)i0 * L + lane];
            float2 b = H2[(size_t)i1 * L + lane];
            float2 c = H2[(size_t)i2 * L + lane];
            float2 d = H2[(size_t)i3 * L + lane];
            ax += (a.x + b.x) + (c.x + d.x);
            ay += (a.y + b.y) + (c.y + d.y);
        }
    }
    for (; j < e; j++) {
        int i0 = g_col[j];
        if (lane < L) {
            float2 a = H2[(size_t)i0 * L + lane];
            ax += a.x; ay += a.y;
        }
    }

    if (lane < L) {
        float dn = g_dis[warp];
        float2 bv = ((const float2*)bias)[lane];
        float ox = fmaf(ax, dn, bv.x);
        float oy = fmaf(ay, dn, bv.y);
        if (RELU) { ox = fmaxf(ox, 0.f); oy = fmaxf(oy, 0.f); }
        float2 r; r.x = ox; r.y = oy;
        ((float2*)out)[(size_t)warp * L + lane] = r;
    }
}

// ---------------- final aggregation + bias + log_softmax (F=40) ----------------
__global__ void __launch_bounds__(256) k_agg_final(const float* __restrict__ H,
                                                   const float* __restrict__ bias,
                                                   float* __restrict__ out) {
    constexpr int F = FOUT;
    constexpr int L = F / 2;  // 20
    int warp = (blockIdx.x * blockDim.x + threadIdx.x) >> 5;
    int lane = threadIdx.x & 31;
    if (warp >= NN) return;

    const float2* H2 = (const float2*)H;
    int s = g_rowptr[warp];
    int e = g_rowptr[warp + 1];

    float ax = 0.f, ay = 0.f;
    if (lane < L) {
        float2 self = H2[(size_t)warp * L + lane];
        ax = self.x; ay = self.y;
    }
    int j = s;
    for (; j + 4 <= e; j += 4) {
        int i0 = g_col[j], i1 = g_col[j + 1], i2 = g_col[j + 2], i3 = g_col[j + 3];
        if (lane < L) {
            float2 a = H2[(size_t)i0 * L + lane];
            float2 b = H2[(size_t)i1 * L + lane];
            float2 c = H2[(size_t)i2 * L + lane];
            float2 d = H2[(size_t)i3 * L + lane];
            ax += (a.x + b.x) + (c.x + d.x);
            ay += (a.y + b.y) + (c.y + d.y);
        }
    }
    for (; j < e; j++) {
        int i0 = g_col[j];
        if (lane < L) {
            float2 a = H2[(size_t)i0 * L + lane];
            ax += a.x; ay += a.y;
        }
    }

    float vx = -INFINITY, vy = -INFINITY;
    if (lane < L) {
        float dn = g_dis[warp];
        float2 bv = ((const float2*)bias)[lane];
        vx = fmaf(ax, dn, bv.x);
        vy = fmaf(ay, dn, bv.y);
    }

    // warp-wide max over 40 values
    float m = fmaxf(vx, vy);
#pragma unroll
    for (int off = 16; off > 0; off >>= 1)
        m = fmaxf(m, __shfl_xor_sync(0xFFFFFFFFu, m, off));

    float se = 0.f;
    if (lane < L) se = expf(vx - m) + expf(vy - m);
#pragma unroll
    for (int off = 16; off > 0; off >>= 1)
        se += __shfl_xor_sync(0xFFFFFFFFu, se, off);

    float ls = logf(se);
    if (lane < L) {
        float2 r; r.x = vx - m - ls; r.y = vy - m - ls;
        ((float2*)out)[(size_t)warp * L + lane] = r;
    }
}

// ---------------- launch ----------------
extern "C" void kernel_launch(void* const* d_in, const int* in_sizes, int n_in,
                              void* d_out, int out_size) {
    const float* x  = (const float*)d_in[0];
    const void*  ei = d_in[1];
    const float* W1 = (const float*)d_in[2];
    const float* b1 = (const float*)d_in[3];
    const float* W2 = (const float*)d_in[4];
    const float* b2 = (const float*)d_in[5];
    const float* W3 = (const float*)d_in[6];
    const float* b3 = (const float*)d_in[7];

    void *pH = nullptr, *pZ = nullptr;
    cudaGetSymbolAddress(&pH, g_H);
    cudaGetSymbolAddress(&pZ, g_Z);
    float* H = (float*)pH;
    float* Z = (float*)pZ;

    const int TB = 256;
    int gN = (NN + TB - 1) / TB;
    int gE = (NE + TB - 1) / TB;
    int gGemm = (NN + 63) / 64;
    int gAgg  = (NN * 32 + TB - 1) / TB;  // warp per node

    // CSR build (recomputed every call; deterministic output up to fp sum order)
    k_detect<<<1, 32>>>((const int*)ei);
    k_init<<<gN, TB>>>();
    k_hist<<<gE, TB>>>(ei);
    k_dis<<<gN, TB>>>();
    k_scan1<<<NBLK, SCAN_B>>>();
    k_scan2<<<1, 128>>>();
    k_scan3<<<gN, TB>>>();
    k_cursor<<<gN, TB>>>();
    k_fill<<<gE, TB>>>(ei);

    // Layer 1: H = dis .* (x @ W1); Z = relu(dis .* aggregate(H) + b1)
    k_gemm<FIN, FHID><<<gGemm, 128>>>(x, W1, H);
    k_agg<FHID, true><<<gAgg, TB>>>(H, b1, Z);

    // Layer 2
    k_gemm<FHID, FHID><<<gGemm, 128>>>(Z, W2, H);
    k_agg<FHID, true><<<gAgg, TB>>>(H, b2, Z);

    // Layer 3 + log_softmax
    k_gemm<FHID, FOUT><<<gGemm, 128>>>(Z, W3, H);
    k_agg_final<<<gAgg, TB>>>(H, b3, (float*)d_out);
}

// round 3
// speedup vs baseline: 1.0721x; 1.0721x over previous
#include <cuda_runtime.h>
#include <math.h>

#define NN 100000
#define NE 1200000
#define FIN 128
#define FHID 64
#define FOUT 40

typedef unsigned long long ull;

// ---------------- scratch (device globals: sanctioned, no allocation) ----------------
__device__ int   g_deg[NN];
__device__ int   g_rowptr[NN + 1];
__device__ int   g_cursor[NN];
__device__ int   g_col[NE];
__device__ float g_dis[NN];
__device__ float g_H[(size_t)NN * FHID];  // dis-scaled transform buffer
__device__ float g_Z[(size_t)NN * FHID];  // aggregated buffer
__device__ int   g_blksum[128];
__device__ int   g_blkoff[128];
__device__ int   g_is64;

constexpr int SCAN_B = 1024;
constexpr int NBLK   = (NN + SCAN_B - 1) / SCAN_B;  // 98

// ---------------- packed f32x2 helpers (Blackwell FFMA2) ----------------
__device__ __forceinline__ ull bcast2(float f) {
    ull r;
    asm("mov.b64 %0, {%1, %1};" : "=l"(r) : "f"(f));
    return r;
}
__device__ __forceinline__ void fma2(ull& d, ull a, ull b) {
    asm("fma.rn.f32x2 %0, %1, %2, %0;" : "+l"(d) : "l"(a), "l"(b));
}
__device__ __forceinline__ void unpack2(float& lo, float& hi, ull v) {
    asm("mov.b64 {%0, %1}, %2;" : "=f"(lo), "=f"(hi) : "l"(v));
}

// ---------------- edge dtype detection (int64 vs int32) ----------------
__global__ void k_detect(const int* __restrict__ e) {
    if (threadIdx.x == 0) {
        int f = 1;
        for (int i = 1; i < 256; i += 2)
            if (e[i] != 0) { f = 0; break; }
        g_is64 = f;
    }
}

__device__ __forceinline__ int edge_at(const void* e, long long idx) {
    if (g_is64) return (int)((const long long*)e)[idx];
    return ((const int*)e)[idx];
}

// ---------------- degree histogram ----------------
__global__ void k_hist(const void* __restrict__ e) {
    int i = blockIdx.x * blockDim.x + threadIdx.x;
    if (i < NE) {
        int d = edge_at(e, (long long)NE + i);
        atomicAdd(&g_deg[d], 1);
    }
}

// ---------------- prefix scan (3 kernels); scan1 also computes dis ----------------
__global__ void k_scan1() {
    __shared__ int s[SCAN_B];
    int tid = threadIdx.x;
    int idx = blockIdx.x * SCAN_B + tid;
    int v = (idx < NN) ? g_deg[idx] : 0;
    if (idx < NN) g_dis[idx] = rsqrtf((float)(v + 1));
    s[tid] = v;
    __syncthreads();
#pragma unroll
    for (int off = 1; off < SCAN_B; off <<= 1) {
        int t = (tid >= off) ? s[tid - off] : 0;
        __syncthreads();
        s[tid] += t;
        __syncthreads();
    }
    if (idx < NN) g_rowptr[idx + 1] = s[tid];
    if (tid == SCAN_B - 1) g_blksum[blockIdx.x] = s[tid];
}

__global__ void k_scan2() {
    __shared__ int s[128];
    int tid = threadIdx.x;
    int v = (tid < NBLK) ? g_blksum[tid] : 0;
    s[tid] = v;
    __syncthreads();
#pragma unroll
    for (int off = 1; off < 128; off <<= 1) {
        int t = (tid >= off) ? s[tid - off] : 0;
        __syncthreads();
        s[tid] += t;
        __syncthreads();
    }
    g_blkoff[tid] = s[tid] - v;  // exclusive
}

__global__ void k_scan3() {
    int i = blockIdx.x * blockDim.x + threadIdx.x;
    if (i < NN) {
        int v = g_rowptr[i + 1] + g_blkoff[i >> 10];
        g_rowptr[i + 1] = v;
        if (i + 1 < NN) g_cursor[i + 1] = v;  // cursor = exclusive prefix
    }
    if (i == 0) { g_rowptr[0] = 0; g_cursor[0] = 0; }
}

__global__ void k_fill(const void* __restrict__ e) {
    int i = blockIdx.x * blockDim.x + threadIdx.x;
    if (i < NE) {
        int d = edge_at(e, (long long)NE + i);
        int s = edge_at(e, i);
        int pos = atomicAdd(&g_cursor[d], 1);
        g_col[pos] = s;
    }
}

// ---------------- GEMM: out[i,c] = dis[i] * sum_k X[i,k]*W[k,c] ----------------
// Tile 64(M) x 64(N), 128 threads; per thread 8 rows x 4 cols as
// 4 row-pairs x 4 cols of packed f32x2 (FFMA2).
template <int K, int NOUT>
__global__ void __launch_bounds__(128) k_gemm(const float* __restrict__ X,
                                              const float* __restrict__ W,
                                              float* __restrict__ out) {
    constexpr int BM = 64;
    constexpr int BN = 64;
    constexpr int KC = 32;
    __shared__ float Ws[K][BN];
    __shared__ float Xs[KC][BM + 4];  // pad: stride 68 floats (272B, 16B-aligned)

    int t  = threadIdx.x;
    int m0 = blockIdx.x * BM;
    int rbase = (t >> 4) * 8;   // 0..56 (multiple of 8)
    int cbase = (t & 15) * 4;   // 0..60

    // load W (zero-pad cols >= NOUT)
    for (int i = t; i < K * BN; i += 128) {
        int k = i / BN, c = i % BN;
        Ws[k][c] = (c < NOUT) ? W[k * NOUT + c] : 0.0f;
    }

    ull acc[4][4];  // [row-pair][col] packed f32x2
#pragma unroll
    for (int rp = 0; rp < 4; rp++)
#pragma unroll
        for (int c = 0; c < 4; c++) acc[rp][c] = 0ull;

    __syncthreads();

    for (int kc = 0; kc < K; kc += KC) {
        // load X chunk transposed: Xs[kk][row]
#pragma unroll
        for (int i = 0; i < 4; i++) {
            int v = t + i * 128;      // 0..511
            int r = v >> 3;           // 0..63
            int q = v & 7;            // float4 within 32-float chunk
            int row = m0 + r;
            float4 f = make_float4(0.f, 0.f, 0.f, 0.f);
            if (row < NN)
                f = *(const float4*)&X[(size_t)row * K + kc + q * 4];
            Xs[q * 4 + 0][r] = f.x;
            Xs[q * 4 + 1][r] = f.y;
            Xs[q * 4 + 2][r] = f.z;
            Xs[q * 4 + 3][r] = f.w;
        }
        __syncthreads();

#pragma unroll
        for (int kk = 0; kk < KC; kk++) {
            float4 wv = *(const float4*)&Ws[kc + kk][cbase];
            ull wb0 = bcast2(wv.x);
            ull wb1 = bcast2(wv.y);
            ull wb2 = bcast2(wv.z);
            ull wb3 = bcast2(wv.w);
            ulonglong2 xp0 = *(const ulonglong2*)&Xs[kk][rbase];
            ulonglong2 xp1 = *(const ulonglong2*)&Xs[kk][rbase + 4];
            ull xr[4] = {xp0.x, xp0.y, xp1.x, xp1.y};
#pragma unroll
            for (int rp = 0; rp < 4; rp++) {
                fma2(acc[rp][0], xr[rp], wb0);
                fma2(acc[rp][1], xr[rp], wb1);
                fma2(acc[rp][2], xr[rp], wb2);
                fma2(acc[rp][3], xr[rp], wb3);
            }
        }
        __syncthreads();
    }

    // epilogue: unpack, scale by dis[row]
#pragma unroll
    for (int rp = 0; rp < 4; rp++) {
        int row0 = m0 + rbase + 2 * rp;
        int row1 = row0 + 1;
        float ds0 = (row0 < NN) ? g_dis[row0] : 0.f;
        float ds1 = (row1 < NN) ? g_dis[row1] : 0.f;
#pragma unroll
        for (int c = 0; c < 4; c++) {
            int cc = cbase + c;
            float lo, hi;
            unpack2(lo, hi, acc[rp][c]);
            if (cc < NOUT) {
                if (row0 < NN) out[(size_t)row0 * NOUT + cc] = lo * ds0;
                if (row1 < NN) out[(size_t)row1 * NOUT + cc] = hi * ds1;
            }
        }
    }
}

// ---------------- aggregation: warp per node ----------------
// out[i] = relu?( dis[i]*(sum_{s->i} Hs[s] + Hs[i]) + b )
template <int F, bool RELU>
__global__ void __launch_bounds__(256) k_agg(const float* __restrict__ H,
                                             const float* __restrict__ bias,
                                             float* __restrict__ out) {
    constexpr int L = F / 2;  // active lanes (float2 each)
    int warp = (blockIdx.x * blockDim.x + threadIdx.x) >> 5;
    int lane = threadIdx.x & 31;
    if (warp >= NN) return;

    const float2* H2 = (const float2*)H;
    int s = g_rowptr[warp];
    int e = g_rowptr[warp + 1];

    float ax = 0.f, ay = 0.f;
    if (lane < L) {
        float2 self = H2[(size_t)warp * L + lane];
        ax = self.x; ay = self.y;
    }

    int j = s;
    for (; j + 4 <= e; j += 4) {
        int i0 = g_col[j], i1 = g_col[j + 1], i2 = g_col[j + 2], i3 = g_col[j + 3];
        if (lane < L) {
            float2 a = H2[(size_t)i0 * L + lane];
            float2 b = H2[(size_t)i1 * L + lane];
            float2 c = H2[(size_t)i2 * L + lane];
            float2 d = H2[(size_t)i3 * L + lane];
            ax += (a.x + b.x) + (c.x + d.x);
            ay += (a.y + b.y) + (c.y + d.y);
        }
    }
    for (; j < e; j++) {
        int i0 = g_col[j];
        if (lane < L) {
            float2 a = H2[(size_t)i0 * L + lane];
            ax += a.x; ay += a.y;
        }
    }

    if (lane < L) {
        float dn = g_dis[warp];
        float2 bv = ((const float2*)bias)[lane];
        float ox = fmaf(ax, dn, bv.x);
        float oy = fmaf(ay, dn, bv.y);
        if (RELU) { ox = fmaxf(ox, 0.f); oy = fmaxf(oy, 0.f); }
        float2 r; r.x = ox; r.y = oy;
        ((float2*)out)[(size_t)warp * L + lane] = r;
    }
}

// ---------------- final aggregation + bias + log_softmax (F=40) ----------------
__global__ void __launch_bounds__(256) k_agg_final(const float* __restrict__ H,
                                                   const float* __restrict__ bias,
                                                   float* __restrict__ out) {
    constexpr int F = FOUT;
    constexpr int L = F / 2;  // 20
    int warp = (blockIdx.x * blockDim.x + threadIdx.x) >> 5;
    int lane = threadIdx.x & 31;
    if (warp >= NN) return;

    const float2* H2 = (const float2*)H;
    int s = g_rowptr[warp];
    int e = g_rowptr[warp + 1];

    float ax = 0.f, ay = 0.f;
    if (lane < L) {
        float2 self = H2[(size_t)warp * L + lane];
        ax = self.x; ay = self.y;
    }
    int j = s;
    for (; j + 4 <= e; j += 4) {
        int i0 = g_col[j], i1 = g_col[j + 1], i2 = g_col[j + 2], i3 = g_col[j + 3];
        if (lane < L) {
            float2 a = H2[(size_t)i0 * L + lane];
            float2 b = H2[(size_t)i1 * L + lane];
            float2 c = H2[(size_t)i2 * L + lane];
            float2 d = H2[(size_t)i3 * L + lane];
            ax += (a.x + b.x) + (c.x + d.x);
            ay += (a.y + b.y) + (c.y + d.y);
        }
    }
    for (; j < e; j++) {
        int i0 = g_col[j];
        if (lane < L) {
            float2 a = H2[(size_t)i0 * L + lane];
            ax += a.x; ay += a.y;
        }
    }

    float vx = -INFINITY, vy = -INFINITY;
    if (lane < L) {
        float dn = g_dis[warp];
        float2 bv = ((const float2*)bias)[lane];
        vx = fmaf(ax, dn, bv.x);
        vy = fmaf(ay, dn, bv.y);
    }

    // warp-wide max over 40 values
    float m = fmaxf(vx, vy);
#pragma unroll
    for (int off = 16; off > 0; off >>= 1)
        m = fmaxf(m, __shfl_xor_sync(0xFFFFFFFFu, m, off));

    float se = 0.f;
    if (lane < L) se = expf(vx - m) + expf(vy - m);
#pragma unroll
    for (int off = 16; off > 0; off >>= 1)
        se += __shfl_xor_sync(0xFFFFFFFFu, se, off);

    float ls = logf(se);
    if (lane < L) {
        float2 r; r.x = vx - m - ls; r.y = vy - m - ls;
        ((float2*)out)[(size_t)warp * L + lane] = r;
    }
}

// ---------------- launch ----------------
extern "C" void kernel_launch(void* const* d_in, const int* in_sizes, int n_in,
                              void* d_out, int out_size) {
    const float* x  = (const float*)d_in[0];
    const void*  ei = d_in[1];
    const float* W1 = (const float*)d_in[2];
    const float* b1 = (const float*)d_in[3];
    const float* W2 = (const float*)d_in[4];
    const float* b2 = (const float*)d_in[5];
    const float* W3 = (const float*)d_in[6];
    const float* b3 = (const float*)d_in[7];

    void *pH = nullptr, *pZ = nullptr, *pDeg = nullptr;
    cudaGetSymbolAddress(&pH, g_H);
    cudaGetSymbolAddress(&pZ, g_Z);
    cudaGetSymbolAddress(&pDeg, g_deg);
    float* H = (float*)pH;
    float* Z = (float*)pZ;

    const int TB = 256;
    int gN = (NN + TB - 1) / TB;
    int gE = (NE + TB - 1) / TB;
    int gGemm = (NN + 63) / 64;
    int gAgg  = (NN * 32 + TB - 1) / TB;  // warp per node

    // CSR build (recomputed every call)
    k_detect<<<1, 32>>>((const int*)ei);
    cudaMemsetAsync(pDeg, 0, NN * sizeof(int));
    k_hist<<<gE, TB>>>(ei);
    k_scan1<<<NBLK, SCAN_B>>>();      // also computes g_dis
    k_scan2<<<1, 128>>>();
    k_scan3<<<gN, TB>>>();            // also initializes g_cursor
    k_fill<<<gE, TB>>>(ei);

    // Layer 1: H = dis .* (x @ W1); Z = relu(dis .* aggregate(H) + b1)
    k_gemm<FIN, FHID><<<gGemm, 128>>>(x, W1, H);
    k_agg<FHID, true><<<gAgg, TB>>>(H, b1, Z);

    // Layer 2
    k_gemm<FHID, FHID><<<gGemm, 128>>>(Z, W2, H);
    k_agg<FHID, true><<<gAgg, TB>>>(H, b2, Z);

    // Layer 3 + log_softmax
    k_gemm<FHID, FOUT><<<gGemm, 128>>>(Z, W3, H);
    k_agg_final<<<gAgg, TB>>>(H, b3, (float*)d_out);
}

// round 4
// speedup vs baseline: 1.1359x; 1.0595x over previous
#include <cuda_runtime.h>
#include <math.h>

#define NN 100000
#define NE 1200000
#define FIN 128
#define FHID 64
#define FOUT 40

typedef unsigned long long ull;

// ---------------- scratch (device globals) ----------------
// g_zero: [0,NN) = degree histogram, [NN, NN+128) = scan ready-flags. One memset.
__device__ int   g_zero[NN + 128];
__device__ int   g_rowptr[NN + 1];
__device__ int   g_cursor[NN];
__device__ int   g_col[NE];
__device__ float g_dis[NN];
__device__ float g_H[(size_t)NN * FHID];
__device__ float g_Z[(size_t)NN * FHID];
__device__ int   g_is64;

constexpr int SCAN_B = 1024;
constexpr int NBLK   = (NN + SCAN_B - 1) / SCAN_B;  // 98

// ---------------- side stream for capture fork-join (created pre-main) ----------------
struct SideStream {
    cudaStream_t s1;
    cudaEvent_t evFork, evJoin;
    SideStream() {
        cudaStreamCreateWithFlags(&s1, cudaStreamNonBlocking);
        cudaEventCreateWithFlags(&evFork, cudaEventDisableTiming);
        cudaEventCreateWithFlags(&evJoin, cudaEventDisableTiming);
    }
};
static SideStream g_ss;

// ---------------- packed f32x2 helpers (Blackwell FFMA2) ----------------
__device__ __forceinline__ ull bcast2(float f) {
    ull r;
    asm("mov.b64 %0, {%1, %1};" : "=l"(r) : "f"(f));
    return r;
}
__device__ __forceinline__ void fma2(ull& d, ull a, ull b) {
    asm("fma.rn.f32x2 %0, %1, %2, %0;" : "+l"(d) : "l"(a), "l"(b));
}
__device__ __forceinline__ void unpack2(float& lo, float& hi, ull v) {
    asm("mov.b64 {%0, %1}, %2;" : "=f"(lo), "=f"(hi) : "l"(v));
}

// ---------------- edge dtype detection (int64 vs int32) ----------------
__global__ void k_detect(const int* __restrict__ e) {
    if (threadIdx.x == 0) {
        int f = 1;
        for (int i = 1; i < 256; i += 2)
            if (e[i] != 0) { f = 0; break; }
        g_is64 = f;
    }
}

__device__ __forceinline__ int edge_at(const void* e, long long idx) {
    if (g_is64) return (int)((const long long*)e)[idx];
    return ((const int*)e)[idx];
}

// ---------------- degree histogram ----------------
__global__ void k_hist(const void* __restrict__ e) {
    int i = blockIdx.x * blockDim.x + threadIdx.x;
    if (i < NE) {
        int d = edge_at(e, (long long)NE + i);
        atomicAdd(&g_zero[d], 1);
    }
}

// ---------------- single-pass scan: deg -> rowptr, cursor, dis ----------------
// 98 blocks (all co-resident on 148 SMs): local scan, publish aggregate,
// poll+sum predecessors' aggregates.
__global__ void __launch_bounds__(SCAN_B) k_scan_fused() {
    __shared__ int s[SCAN_B];
    __shared__ int s_off;
    int b   = blockIdx.x;
    int tid = threadIdx.x;
    int idx = b * SCAN_B + tid;
    int* ready = &g_zero[NN];

    int v = (idx < NN) ? g_zero[idx] : 0;
    if (idx < NN) g_dis[idx] = rsqrtf((float)(v + 1));
    s[tid] = v;
    if (tid == 0) s_off = 0;
    __syncthreads();
#pragma unroll
    for (int off = 1; off < SCAN_B; off <<= 1) {
        int t = (tid >= off) ? s[tid - off] : 0;
        __syncthreads();
        s[tid] += t;
        __syncthreads();
    }
    int inc = s[tid];

    // publish this block's aggregate (value+1; 0 = not ready)
    if (tid == SCAN_B - 1)
        atomicExch(&ready[b], inc + 1);

    // sum predecessors' aggregates
    if (tid < b) {
        int a;
        do { a = atomicAdd(&ready[tid], 0); } while (a == 0);
        atomicAdd(&s_off, a - 1);
    }
    __syncthreads();
    int off = s_off;

    if (idx < NN) {
        int ip = off + inc;
        g_rowptr[idx + 1] = ip;
        g_cursor[idx]     = ip - v;  // exclusive prefix
    }
    if (idx == 0) g_rowptr[0] = 0;
}

__global__ void k_fill(const void* __restrict__ e) {
    int i = blockIdx.x * blockDim.x + threadIdx.x;
    if (i < NE) {
        int d = edge_at(e, (long long)NE + i);
        int s = edge_at(e, i);
        int pos = atomicAdd(&g_cursor[d], 1);
        g_col[pos] = s;
    }
}

// ---------------- GEMM: out[i,c] = (SCALE ? dis[i] : 1) * sum_k X[i,k]*W[k,c] ----------------
template <int K, int NOUT, bool SCALE>
__global__ void __launch_bounds__(128) k_gemm(const float* __restrict__ X,
                                              const float* __restrict__ W,
                                              float* __restrict__ out) {
    constexpr int BM = 64;
    constexpr int BN = 64;
    constexpr int KC = 32;
    __shared__ float Ws[K][BN];
    __shared__ float Xs[KC][BM + 4];

    int t  = threadIdx.x;
    int m0 = blockIdx.x * BM;
    int rbase = (t >> 4) * 8;
    int cbase = (t & 15) * 4;

    for (int i = t; i < K * BN; i += 128) {
        int k = i / BN, c = i % BN;
        Ws[k][c] = (c < NOUT) ? W[k * NOUT + c] : 0.0f;
    }

    ull acc[4][4];
#pragma unroll
    for (int rp = 0; rp < 4; rp++)
#pragma unroll
        for (int c = 0; c < 4; c++) acc[rp][c] = 0ull;

    __syncthreads();

    for (int kc = 0; kc < K; kc += KC) {
#pragma unroll
        for (int i = 0; i < 4; i++) {
            int v = t + i * 128;
            int r = v >> 3;
            int q = v & 7;
            int row = m0 + r;
            float4 f = make_float4(0.f, 0.f, 0.f, 0.f);
            if (row < NN)
                f = *(const float4*)&X[(size_t)row * K + kc + q * 4];
            Xs[q * 4 + 0][r] = f.x;
            Xs[q * 4 + 1][r] = f.y;
            Xs[q * 4 + 2][r] = f.z;
            Xs[q * 4 + 3][r] = f.w;
        }
        __syncthreads();

#pragma unroll
        for (int kk = 0; kk < KC; kk++) {
            float4 wv = *(const float4*)&Ws[kc + kk][cbase];
            ull wb0 = bcast2(wv.x);
            ull wb1 = bcast2(wv.y);
            ull wb2 = bcast2(wv.z);
            ull wb3 = bcast2(wv.w);
            ulonglong2 xp0 = *(const ulonglong2*)&Xs[kk][rbase];
            ulonglong2 xp1 = *(const ulonglong2*)&Xs[kk][rbase + 4];
            ull xr[4] = {xp0.x, xp0.y, xp1.x, xp1.y};
#pragma unroll
            for (int rp = 0; rp < 4; rp++) {
                fma2(acc[rp][0], xr[rp], wb0);
                fma2(acc[rp][1], xr[rp], wb1);
                fma2(acc[rp][2], xr[rp], wb2);
                fma2(acc[rp][3], xr[rp], wb3);
            }
        }
        __syncthreads();
    }

#pragma unroll
    for (int rp = 0; rp < 4; rp++) {
        int row0 = m0 + rbase + 2 * rp;
        int row1 = row0 + 1;
        float ds0 = 1.f, ds1 = 1.f;
        if (SCALE) {
            ds0 = (row0 < NN) ? g_dis[row0] : 0.f;
            ds1 = (row1 < NN) ? g_dis[row1] : 0.f;
        }
#pragma unroll
        for (int c = 0; c < 4; c++) {
            int cc = cbase + c;
            float lo, hi;
            unpack2(lo, hi, acc[rp][c]);
            if (cc < NOUT) {
                if (row0 < NN) out[(size_t)row0 * NOUT + cc] = lo * ds0;
                if (row1 < NN) out[(size_t)row1 * NOUT + cc] = hi * ds1;
            }
        }
    }
}

// ---------------- aggregation: warp per node ----------------
// SRCSCALE=false: H is already dis-scaled; out = relu?(dis[d]*(Σ H[s] + H[d]) + b)
// SRCSCALE=true : H unscaled;            out = relu?(dis[d]*(Σ dis[s]H[s] + dis[d]H[d]) + b)
template <int F, bool RELU, bool SRCSCALE>
__global__ void __launch_bounds__(256) k_agg(const float* __restrict__ H,
                                             const float* __restrict__ bias,
                                             float* __restrict__ out) {
    constexpr int L = F / 2;
    int warp = (blockIdx.x * blockDim.x + threadIdx.x) >> 5;
    int lane = threadIdx.x & 31;
    if (warp >= NN) return;

    const float2* H2 = (const float2*)H;
    int s = g_rowptr[warp];
    int e = g_rowptr[warp + 1];
    float dn = g_dis[warp];

    float ax = 0.f, ay = 0.f;
    if (lane < L) {
        float2 self = H2[(size_t)warp * L + lane];
        float sc = SRCSCALE ? dn : 1.f;
        ax = self.x * sc; ay = self.y * sc;
    }

    int j = s;
    for (; j + 4 <= e; j += 4) {
        int i0 = g_col[j], i1 = g_col[j + 1], i2 = g_col[j + 2], i3 = g_col[j + 3];
        float d0 = 1.f, d1 = 1.f, d2 = 1.f, d3 = 1.f;
        if (SRCSCALE) {
            d0 = g_dis[i0]; d1 = g_dis[i1]; d2 = g_dis[i2]; d3 = g_dis[i3];
        }
        if (lane < L) {
            float2 a = H2[(size_t)i0 * L + lane];
            float2 b = H2[(size_t)i1 * L + lane];
            float2 c = H2[(size_t)i2 * L + lane];
            float2 d = H2[(size_t)i3 * L + lane];
            if (SRCSCALE) {
                ax = fmaf(a.x, d0, ax); ay = fmaf(a.y, d0, ay);
                ax = fmaf(b.x, d1, ax); ay = fmaf(b.y, d1, ay);
                ax = fmaf(c.x, d2, ax); ay = fmaf(c.y, d2, ay);
                ax = fmaf(d.x, d3, ax); ay = fmaf(d.y, d3, ay);
            } else {
                ax += (a.x + b.x) + (c.x + d.x);
                ay += (a.y + b.y) + (c.y + d.y);
            }
        }
    }
    for (; j < e; j++) {
        int i0 = g_col[j];
        float d0 = SRCSCALE ? g_dis[i0] : 1.f;
        if (lane < L) {
            float2 a = H2[(size_t)i0 * L + lane];
            if (SRCSCALE) { ax = fmaf(a.x, d0, ax); ay = fmaf(a.y, d0, ay); }
            else          { ax += a.x; ay += a.y; }
        }
    }

    if (lane < L) {
        float2 bv = ((const float2*)bias)[lane];
        float ox = fmaf(ax, dn, bv.x);
        float oy = fmaf(ay, dn, bv.y);
        if (RELU) { ox = fmaxf(ox, 0.f); oy = fmaxf(oy, 0.f); }
        float2 r; r.x = ox; r.y = oy;
        ((float2*)out)[(size_t)warp * L + lane] = r;
    }
}

// ---------------- final aggregation + bias + log_softmax (F=40) ----------------
__global__ void __launch_bounds__(256) k_agg_final(const float* __restrict__ H,
                                                   const float* __restrict__ bias,
                                                   float* __restrict__ out) {
    constexpr int L = FOUT / 2;  // 20
    int warp = (blockIdx.x * blockDim.x + threadIdx.x) >> 5;
    int lane = threadIdx.x & 31;
    if (warp >= NN) return;

    const float2* H2 = (const float2*)H;
    int s = g_rowptr[warp];
    int e = g_rowptr[warp + 1];

    float ax = 0.f, ay = 0.f;
    if (lane < L) {
        float2 self = H2[(size_t)warp * L + lane];
        ax = self.x; ay = self.y;
    }
    int j = s;
    for (; j + 4 <= e; j += 4) {
        int i0 = g_col[j], i1 = g_col[j + 1], i2 = g_col[j + 2], i3 = g_col[j + 3];
        if (lane < L) {
            float2 a = H2[(size_t)i0 * L + lane];
            float2 b = H2[(size_t)i1 * L + lane];
            float2 c = H2[(size_t)i2 * L + lane];
            float2 d = H2[(size_t)i3 * L + lane];
            ax += (a.x + b.x) + (c.x + d.x);
            ay += (a.y + b.y) + (c.y + d.y);
        }
    }
    for (; j < e; j++) {
        int i0 = g_col[j];
        if (lane < L) {
            float2 a = H2[(size_t)i0 * L + lane];
            ax += a.x; ay += a.y;
        }
    }

    float vx = -INFINITY, vy = -INFINITY;
    if (lane < L) {
        float dn = g_dis[warp];
        float2 bv = ((const float2*)bias)[lane];
        vx = fmaf(ax, dn, bv.x);
        vy = fmaf(ay, dn, bv.y);
    }

    float m = fmaxf(vx, vy);
#pragma unroll
    for (int off = 16; off > 0; off >>= 1)
        m = fmaxf(m, __shfl_xor_sync(0xFFFFFFFFu, m, off));

    float se = 0.f;
    if (lane < L) se = expf(vx - m) + expf(vy - m);
#pragma unroll
    for (int off = 16; off > 0; off >>= 1)
        se += __shfl_xor_sync(0xFFFFFFFFu, se, off);

    float ls = logf(se);
    if (lane < L) {
        float2 r; r.x = vx - m - ls; r.y = vy - m - ls;
        ((float2*)out)[(size_t)warp * L + lane] = r;
    }
}

// ---------------- launch ----------------
extern "C" void kernel_launch(void* const* d_in, const int* in_sizes, int n_in,
                              void* d_out, int out_size) {
    const float* x  = (const float*)d_in[0];
    const void*  ei = d_in[1];
    const float* W1 = (const float*)d_in[2];
    const float* b1 = (const float*)d_in[3];
    const float* W2 = (const float*)d_in[4];
    const float* b2 = (const float*)d_in[5];
    const float* W3 = (const float*)d_in[6];
    const float* b3 = (const float*)d_in[7];

    void *pH = nullptr, *pZ = nullptr, *pZero = nullptr;
    cudaGetSymbolAddress(&pH, g_H);
    cudaGetSymbolAddress(&pZ, g_Z);
    cudaGetSymbolAddress(&pZero, g_zero);
    float* H = (float*)pH;
    float* Z = (float*)pZ;

    const int TB = 256;
    int gE = (NE + TB - 1) / TB;
    int gGemm = (NN + 63) / 64;
    int gAgg  = (NN * 32 + TB - 1) / TB;

    // Fork: GEMM1 (no CSR dependency, dis-scaling deferred to agg1) on side stream,
    // overlapped with the CSR build on the main (capture) stream.
    cudaEventRecord(g_ss.evFork, 0);
    cudaStreamWaitEvent(g_ss.s1, g_ss.evFork, 0);
    k_gemm<FIN, FHID, false><<<gGemm, 128, 0, g_ss.s1>>>(x, W1, H);
    cudaEventRecord(g_ss.evJoin, g_ss.s1);

    // Main stream: CSR build
    k_detect<<<1, 32>>>((const int*)ei);
    cudaMemsetAsync(pZero, 0, (NN + 128) * sizeof(int));
    k_hist<<<gE, TB>>>(ei);
    k_scan_fused<<<NBLK, SCAN_B>>>();
    k_fill<<<gE, TB>>>(ei);

    // Join, then layer 1 aggregation (applies src-side dis)
    cudaStreamWaitEvent(0, g_ss.evJoin, 0);
    k_agg<FHID, true, true><<<gAgg, TB>>>(H, b1, Z);

    // Layer 2 (dis folded into GEMM epilogue as before)
    k_gemm<FHID, FHID, true><<<gGemm, 128>>>(Z, W2, H);
    k_agg<FHID, true, false><<<gAgg, TB>>>(H, b2, Z);

    // Layer 3 + log_softmax
    k_gemm<FHID, FOUT, true><<<gGemm, 128>>>(Z, W3, H);
    k_agg_final<<<gAgg, TB>>>(H, b3, (float*)d_out);
}

// round 5
// speedup vs baseline: 1.1558x; 1.0175x over previous
#include <cuda_runtime.h>
#include <cuda_fp16.h>
#include <math.h>

#define NN 100000
#define NE 1200000
#define FIN 128
#define FHID 64
#define FOUT 40

typedef unsigned long long ull;

// ---------------- scratch (device globals) ----------------
// g_zero: [0,NN) = degree histogram, [NN, NN+128) = scan ready-flags. One memset.
__device__ int    g_zero[NN + 128];
__device__ int    g_rowptr[NN + 1];
__device__ int    g_cursor[NN];
__device__ int    g_col[NE];
__device__ float  g_dis[NN];
__device__ __half g_Hh[(size_t)NN * FHID];  // fp16 message buffer (layers 1-2)
__device__ float  g_H[(size_t)NN * FHID];   // fp32 message buffer (layer 3)
__device__ float  g_Z[(size_t)NN * FHID];   // aggregated fp32 buffer

constexpr int SCAN_B = 1024;
constexpr int NBLK   = (NN + SCAN_B - 1) / SCAN_B;  // 98

// ---------------- side stream for capture fork-join (created pre-main) ----------------
struct SideStream {
    cudaStream_t s1;
    cudaEvent_t evFork, evJoin;
    SideStream() {
        cudaStreamCreateWithFlags(&s1, cudaStreamNonBlocking);
        cudaEventCreateWithFlags(&evFork, cudaEventDisableTiming);
        cudaEventCreateWithFlags(&evJoin, cudaEventDisableTiming);
    }
};
static SideStream g_ss;

// ---------------- packed f32x2 helpers (Blackwell FFMA2) ----------------
__device__ __forceinline__ ull bcast2(float f) {
    ull r;
    asm("mov.b64 %0, {%1, %1};" : "=l"(r) : "f"(f));
    return r;
}
__device__ __forceinline__ void fma2(ull& d, ull a, ull b) {
    asm("fma.rn.f32x2 %0, %1, %2, %0;" : "+l"(d) : "l"(a), "l"(b));
}
__device__ __forceinline__ void unpack2(float& lo, float& hi, ull v) {
    asm("mov.b64 {%0, %1}, %2;" : "=f"(lo), "=f"(hi) : "l"(v));
}

// ---------------- per-block edge dtype detection ----------------
// Returns 1 if edge_index is int64. Each of the first 128 threads checks one odd
// 32-bit word of the first 256 words (int64 values < 2^31 -> high words all 0).
__device__ __forceinline__ int detect_is64(const int* e) {
    int t = threadIdx.x;
    int pred = 1;
    if (t < 128) pred = (e[2 * t + 1] == 0);
    return __syncthreads_and(pred);
}

__device__ __forceinline__ int edge_at(const void* e, long long idx, int is64) {
    if (is64) return (int)((const long long*)e)[idx];
    return ((const int*)e)[idx];
}

// ---------------- degree histogram (detect folded in) ----------------
__global__ void k_hist(const void* __restrict__ e) {
    int is64 = detect_is64((const int*)e);
    int i = blockIdx.x * blockDim.x + threadIdx.x;
    if (i < NE) {
        int d = edge_at(e, (long long)NE + i, is64);
        atomicAdd(&g_zero[d], 1);
    }
}

// ---------------- single-pass scan: deg -> rowptr, cursor, dis ----------------
// 98 co-resident blocks: warp-shuffle local scan, publish aggregate, lookback.
__global__ void __launch_bounds__(SCAN_B) k_scan_fused() {
    __shared__ int wsum[32];
    __shared__ int s_off;
    int b    = blockIdx.x;
    int tid  = threadIdx.x;
    int lane = tid & 31;
    int wid  = tid >> 5;
    int idx  = b * SCAN_B + tid;
    int* ready = &g_zero[NN];

    int v = (idx < NN) ? g_zero[idx] : 0;
    if (idx < NN) g_dis[idx] = rsqrtf((float)(v + 1));
    if (tid == 0) s_off = 0;

    // warp inclusive scan
    int x = v;
#pragma unroll
    for (int off = 1; off < 32; off <<= 1) {
        int y = __shfl_up_sync(0xFFFFFFFFu, x, off);
        if (lane >= off) x += y;
    }
    if (lane == 31) wsum[wid] = x;
    __syncthreads();
    if (wid == 0) {
        int w = wsum[lane];
#pragma unroll
        for (int off = 1; off < 32; off <<= 1) {
            int y = __shfl_up_sync(0xFFFFFFFFu, w, off);
            if (lane >= off) w += y;
        }
        wsum[lane] = w;
    }
    __syncthreads();
    int inc = x + ((wid > 0) ? wsum[wid - 1] : 0);  // block-local inclusive

    // publish this block's aggregate (value+1; 0 = not ready)
    if (tid == SCAN_B - 1)
        atomicExch(&ready[b], inc + 1);

    // lookback: sum predecessors' aggregates
    if (tid < b) {
        int a;
        do { a = atomicAdd(&ready[tid], 0); } while (a == 0);
        atomicAdd(&s_off, a - 1);
    }
    __syncthreads();
    int off = s_off;

    if (idx < NN) {
        int ip = off + inc;
        g_rowptr[idx + 1] = ip;
        g_cursor[idx]     = ip - v;  // exclusive prefix
    }
    if (idx == 0) g_rowptr[0] = 0;
}

__global__ void k_fill(const void* __restrict__ e) {
    int is64 = detect_is64((const int*)e);
    int i = blockIdx.x * blockDim.x + threadIdx.x;
    if (i < NE) {
        int d = edge_at(e, (long long)NE + i, is64);
        int s = edge_at(e, i, is64);
        int pos = atomicAdd(&g_cursor[d], 1);
        g_col[pos] = s;
    }
}

// ---------------- GEMM: out[i,c] = (SCALE ? dis[i] : 1) * sum_k X[i,k]*W[k,c] ----------------
// OUTH: write __half output (requires NOUT == 64).
template <int K, int NOUT, bool SCALE, bool OUTH>
__global__ void __launch_bounds__(128) k_gemm(const float* __restrict__ X,
                                              const float* __restrict__ W,
                                              void* __restrict__ outv) {
    constexpr int BM = 64;
    constexpr int BN = 64;
    constexpr int KC = 32;
    __shared__ float Ws[K][BN];
    __shared__ float Xs[KC][BM + 4];

    int t  = threadIdx.x;
    int m0 = blockIdx.x * BM;
    int rbase = (t >> 4) * 8;
    int cbase = (t & 15) * 4;

    for (int i = t; i < K * BN; i += 128) {
        int k = i / BN, c = i % BN;
        Ws[k][c] = (c < NOUT) ? W[k * NOUT + c] : 0.0f;
    }

    ull acc[4][4];
#pragma unroll
    for (int rp = 0; rp < 4; rp++)
#pragma unroll
        for (int c = 0; c < 4; c++) acc[rp][c] = 0ull;

    __syncthreads();

    for (int kc = 0; kc < K; kc += KC) {
#pragma unroll
        for (int i = 0; i < 4; i++) {
            int v = t + i * 128;
            int r = v >> 3;
            int q = v & 7;
            int row = m0 + r;
            float4 f = make_float4(0.f, 0.f, 0.f, 0.f);
            if (row < NN)
                f = *(const float4*)&X[(size_t)row * K + kc + q * 4];
            Xs[q * 4 + 0][r] = f.x;
            Xs[q * 4 + 1][r] = f.y;
            Xs[q * 4 + 2][r] = f.z;
            Xs[q * 4 + 3][r] = f.w;
        }
        __syncthreads();

#pragma unroll
        for (int kk = 0; kk < KC; kk++) {
            float4 wv = *(const float4*)&Ws[kc + kk][cbase];
            ull wb0 = bcast2(wv.x);
            ull wb1 = bcast2(wv.y);
            ull wb2 = bcast2(wv.z);
            ull wb3 = bcast2(wv.w);
            ulonglong2 xp0 = *(const ulonglong2*)&Xs[kk][rbase];
            ulonglong2 xp1 = *(const ulonglong2*)&Xs[kk][rbase + 4];
            ull xr[4] = {xp0.x, xp0.y, xp1.x, xp1.y};
#pragma unroll
            for (int rp = 0; rp < 4; rp++) {
                fma2(acc[rp][0], xr[rp], wb0);
                fma2(acc[rp][1], xr[rp], wb1);
                fma2(acc[rp][2], xr[rp], wb2);
                fma2(acc[rp][3], xr[rp], wb3);
            }
        }
        __syncthreads();
    }

#pragma unroll
    for (int rp = 0; rp < 4; rp++) {
        int row0 = m0 + rbase + 2 * rp;
        int row1 = row0 + 1;
        float ds0 = 1.f, ds1 = 1.f;
        if (SCALE) {
            ds0 = (row0 < NN) ? g_dis[row0] : 0.f;
            ds1 = (row1 < NN) ? g_dis[row1] : 0.f;
        }
        float v0[4], v1[4];
#pragma unroll
        for (int c = 0; c < 4; c++) unpack2(v0[c], v1[c], acc[rp][c]);

        if (OUTH) {
            __half* out = (__half*)outv;
            if (row0 < NN) {
                __half2* p = (__half2*)&out[(size_t)row0 * NOUT + cbase];
                p[0] = __floats2half2_rn(v0[0] * ds0, v0[1] * ds0);
                p[1] = __floats2half2_rn(v0[2] * ds0, v0[3] * ds0);
            }
            if (row1 < NN) {
                __half2* p = (__half2*)&out[(size_t)row1 * NOUT + cbase];
                p[0] = __floats2half2_rn(v1[0] * ds1, v1[1] * ds1);
                p[1] = __floats2half2_rn(v1[2] * ds1, v1[3] * ds1);
            }
        } else {
            float* out = (float*)outv;
#pragma unroll
            for (int c = 0; c < 4; c++) {
                int cc = cbase + c;
                if (cc < NOUT) {
                    if (row0 < NN) out[(size_t)row0 * NOUT + cc] = v0[c] * ds0;
                    if (row1 < NN) out[(size_t)row1 * NOUT + cc] = v1[c] * ds1;
                }
            }
        }
    }
}

// ---------------- fp16 aggregation (F=64): warp per node, fp32 accumulate ----------------
// SRCSCALE=false: H pre-scaled by dis; out = relu(dis[d]*(Σ H[s] + H[d]) + b)
// SRCSCALE=true : H unscaled;         out = relu(dis[d]*(Σ dis[s]H[s] + dis[d]H[d]) + b)
template <bool SRCSCALE>
__global__ void __launch_bounds__(256) k_agg_h(const __half2* __restrict__ H,
                                               const float* __restrict__ bias,
                                               float* __restrict__ out) {
    constexpr int L = FHID / 2;  // 32 half2 per row = full warp
    int warp = (blockIdx.x * blockDim.x + threadIdx.x) >> 5;
    int lane = threadIdx.x & 31;
    if (warp >= NN) return;

    int s = g_rowptr[warp];
    int e = g_rowptr[warp + 1];
    float dn = g_dis[warp];

    float2 self = __half22float2(H[(size_t)warp * L + lane]);
    float sc = SRCSCALE ? dn : 1.f;
    float ax = self.x * sc, ay = self.y * sc;

    int j = s;
    for (; j + 4 <= e; j += 4) {
        int i0 = g_col[j], i1 = g_col[j + 1], i2 = g_col[j + 2], i3 = g_col[j + 3];
        float2 a = __half22float2(H[(size_t)i0 * L + lane]);
        float2 b = __half22float2(H[(size_t)i1 * L + lane]);
        float2 c = __half22float2(H[(size_t)i2 * L + lane]);
        float2 d = __half22float2(H[(size_t)i3 * L + lane]);
        if (SRCSCALE) {
            float d0 = g_dis[i0], d1 = g_dis[i1], d2 = g_dis[i2], d3 = g_dis[i3];
            ax = fmaf(a.x, d0, ax); ay = fmaf(a.y, d0, ay);
            ax = fmaf(b.x, d1, ax); ay = fmaf(b.y, d1, ay);
            ax = fmaf(c.x, d2, ax); ay = fmaf(c.y, d2, ay);
            ax = fmaf(d.x, d3, ax); ay = fmaf(d.y, d3, ay);
        } else {
            ax += (a.x + b.x) + (c.x + d.x);
            ay += (a.y + b.y) + (c.y + d.y);
        }
    }
    for (; j < e; j++) {
        int i0 = g_col[j];
        float2 a = __half22float2(H[(size_t)i0 * L + lane]);
        if (SRCSCALE) {
            float d0 = g_dis[i0];
            ax = fmaf(a.x, d0, ax); ay = fmaf(a.y, d0, ay);
        } else {
            ax += a.x; ay += a.y;
        }
    }

    float2 bv = ((const float2*)bias)[lane];
    float ox = fmaxf(fmaf(ax, dn, bv.x), 0.f);
    float oy = fmaxf(fmaf(ay, dn, bv.y), 0.f);
    float2 r; r.x = ox; r.y = oy;
    ((float2*)out)[(size_t)warp * L + lane] = r;
}

// ---------------- final aggregation + bias + log_softmax (F=40, fp32) ----------------
__global__ void __launch_bounds__(256) k_agg_final(const float* __restrict__ H,
                                                   const float* __restrict__ bias,
                                                   float* __restrict__ out) {
    constexpr int L = FOUT / 2;  // 20
    int warp = (blockIdx.x * blockDim.x + threadIdx.x) >> 5;
    int lane = threadIdx.x & 31;
    if (warp >= NN) return;

    const float2* H2 = (const float2*)H;
    int s = g_rowptr[warp];
    int e = g_rowptr[warp + 1];

    float ax = 0.f, ay = 0.f;
    if (lane < L) {
        float2 self = H2[(size_t)warp * L + lane];
        ax = self.x; ay = self.y;
    }
    int j = s;
    for (; j + 4 <= e; j += 4) {
        int i0 = g_col[j], i1 = g_col[j + 1], i2 = g_col[j + 2], i3 = g_col[j + 3];
        if (lane < L) {
            float2 a = H2[(size_t)i0 * L + lane];
            float2 b = H2[(size_t)i1 * L + lane];
            float2 c = H2[(size_t)i2 * L + lane];
            float2 d = H2[(size_t)i3 * L + lane];
            ax += (a.x + b.x) + (c.x + d.x);
            ay += (a.y + b.y) + (c.y + d.y);
        }
    }
    for (; j < e; j++) {
        int i0 = g_col[j];
        if (lane < L) {
            float2 a = H2[(size_t)i0 * L + lane];
            ax += a.x; ay += a.y;
        }
    }

    float vx = -INFINITY, vy = -INFINITY;
    if (lane < L) {
        float dn = g_dis[warp];
        float2 bv = ((const float2*)bias)[lane];
        vx = fmaf(ax, dn, bv.x);
        vy = fmaf(ay, dn, bv.y);
    }

    float m = fmaxf(vx, vy);
#pragma unroll
    for (int off = 16; off > 0; off >>= 1)
        m = fmaxf(m, __shfl_xor_sync(0xFFFFFFFFu, m, off));

    float se = 0.f;
    if (lane < L) se = expf(vx - m) + expf(vy - m);
#pragma unroll
    for (int off = 16; off > 0; off >>= 1)
        se += __shfl_xor_sync(0xFFFFFFFFu, se, off);

    float ls = logf(se);
    if (lane < L) {
        float2 r; r.x = vx - m - ls; r.y = vy - m - ls;
        ((float2*)out)[(size_t)warp * L + lane] = r;
    }
}

// ---------------- launch ----------------
extern "C" void kernel_launch(void* const* d_in, const int* in_sizes, int n_in,
                              void* d_out, int out_size) {
    const float* x  = (const float*)d_in[0];
    const void*  ei = d_in[1];
    const float* W1 = (const float*)d_in[2];
    const float* b1 = (const float*)d_in[3];
    const float* W2 = (const float*)d_in[4];
    const float* b2 = (const float*)d_in[5];
    const float* W3 = (const float*)d_in[6];
    const float* b3 = (const float*)d_in[7];

    void *pH = nullptr, *pHh = nullptr, *pZ = nullptr, *pZero = nullptr;
    cudaGetSymbolAddress(&pH, g_H);
    cudaGetSymbolAddress(&pHh, g_Hh);
    cudaGetSymbolAddress(&pZ, g_Z);
    cudaGetSymbolAddress(&pZero, g_zero);
    float*   H  = (float*)pH;
    __half2* Hh = (__half2*)pHh;
    float*   Z  = (float*)pZ;

    const int TB = 256;
    int gE = (NE + TB - 1) / TB;
    int gGemm = (NN + 63) / 64;
    int gAgg  = (NN * 32 + TB - 1) / TB;

    // Fork: GEMM1 (no CSR dependency; dis-scaling deferred to agg1) overlapped
    // with the CSR build.
    cudaEventRecord(g_ss.evFork, 0);
    cudaStreamWaitEvent(g_ss.s1, g_ss.evFork, 0);
    k_gemm<FIN, FHID, false, true><<<gGemm, 128, 0, g_ss.s1>>>(x, W1, pHh);
    cudaEventRecord(g_ss.evJoin, g_ss.s1);

    // Main stream: CSR build
    cudaMemsetAsync(pZero, 0, (NN + 128) * sizeof(int));
    k_hist<<<gE, TB>>>(ei);
    k_scan_fused<<<NBLK, SCAN_B>>>();
    k_fill<<<gE, TB>>>(ei);

    // Join, then layer 1 aggregation (applies src-side dis)
    cudaStreamWaitEvent(0, g_ss.evJoin, 0);
    k_agg_h<true><<<gAgg, TB>>>(Hh, b1, Z);

    // Layer 2 (dis folded into GEMM epilogue)
    k_gemm<FHID, FHID, true, true><<<gGemm, 128>>>(Z, W2, pHh);
    k_agg_h<false><<<gAgg, TB>>>(Hh, b2, Z);

    // Layer 3 + log_softmax (fp32 messages)
    k_gemm<FHID, FOUT, true, false><<<gGemm, 128>>>(Z, W3, pH);
    k_agg_final<<<gAgg, TB>>>(H, b3, (float*)d_out);
}